// round 7
// baseline (speedup 1.0000x reference)
#include <cuda_runtime.h>
#include <math.h>

#define N_NEIGH 500000
#define NQ (N_NEIGH / 4)
#define SIZE 64
#define K1_THREADS 256
#define K1_BLOCKS ((NQ + K1_THREADS - 1) / K1_THREADS)
#define K2_BLOCKS 2048
#define K2_TILE 64            // rows per block per iteration (16 groups x 4 rows)

// ---- scratch (no allocations allowed) ----
__device__ __align__(16) float g_w[N_NEIGH];
__device__ float g_t[SIZE];
__device__ float g_Z;
__device__ unsigned int g_count;

// K1: w[j] = exp( sum_i v[i] * nx_flat[i*N + j] )   (raw-reshape column dot)
// v = W^T a2 computed per-block (trivial; W stays L2-hot across blocks).
// No max-shift needed: energies ~N(0,1) for Xavier-scale params; max over
// 500k draws ~4.8 << 88 (fp32 exp overflow). Softmax is shift-invariant.
// Block 0 zeroes the cross-kernel accumulators (graph replays!).
__global__ void k1_energy_exp(const float* __restrict__ nx,
                              const float* __restrict__ W,
                              const float* __restrict__ a) {
    __shared__ float sv[SIZE];
    int tid = threadIdx.x;

    if (tid < SIZE) {
        float s = 0.f;
#pragma unroll
        for (int o = 0; o < SIZE; o++) s = fmaf(a[SIZE + o], W[o * SIZE + tid], s);
        sv[tid] = s;
    }
    if (blockIdx.x == 0) {
        if (tid < SIZE) g_t[tid] = 0.f;
        if (tid == 0) { g_Z = 0.f; g_count = 0u; }
    }
    __syncthreads();

    int q = blockIdx.x * K1_THREADS + tid;  // quad index (j = 4q)
    if (q < NQ) {
        const float4* __restrict__ p = (const float4*)nx;
        float ex = 0.f, ey = 0.f, ez = 0.f, ew = 0.f;
#pragma unroll
        for (int i = 0; i < SIZE; i++) {
            float4 d = p[i * NQ + q];   // slab i, contiguous across threads
            float vi = sv[i];
            ex = fmaf(vi, d.x, ex);
            ey = fmaf(vi, d.y, ey);
            ez = fmaf(vi, d.z, ez);
            ew = fmaf(vi, d.w, ew);
        }
        float4 w;
        w.x = __expf(ex);
        w.y = __expf(ey);
        w.z = __expf(ez);
        w.w = __expf(ew);
        ((float4*)g_w)[q] = w;
    }
}

// K2: t[k] += w[j]*n_x[j][k]; Z += w[j]; last block computes
// out = sigmoid(W @ (t/Z)) in its epilogue (threadFenceReduction pattern).
// 256 threads = 16 groups of 16 lanes; block tile = 64 consecutive rows;
// 5 independent 16B loads in flight per group-iteration.
__global__ void k2_acc(const float* __restrict__ nx,
                       const float* __restrict__ W,
                       float* __restrict__ out) {
    __shared__ float tsh[SIZE];
    __shared__ float zsh;
    __shared__ float agg[SIZE];
    __shared__ bool is_last;
    int tid = threadIdx.x;
    if (tid < SIZE) tsh[tid] = 0.f;
    if (tid == 0) zsh = 0.f;
    __syncthreads();

    const int lane16 = tid & 15;
    const int grp = tid >> 4;  // 0..15
    const float4* __restrict__ p = (const float4*)nx;
    const float4* __restrict__ wv = (const float4*)g_w;

    float4 acc = make_float4(0.f, 0.f, 0.f, 0.f);
    float zacc = 0.f;

    for (int j0 = blockIdx.x * K2_TILE + grp * 4; j0 < N_NEIGH;
         j0 += K2_BLOCKS * K2_TILE) {
        float4 wq = wv[j0 >> 2];                 // uniform addr -> L2 broadcast
        float4 d0 = p[(j0 + 0) * 16 + lane16];
        float4 d1 = p[(j0 + 1) * 16 + lane16];
        float4 d2 = p[(j0 + 2) * 16 + lane16];
        float4 d3 = p[(j0 + 3) * 16 + lane16];
        acc.x = fmaf(wq.x, d0.x, fmaf(wq.y, d1.x, fmaf(wq.z, d2.x, fmaf(wq.w, d3.x, acc.x))));
        acc.y = fmaf(wq.x, d0.y, fmaf(wq.y, d1.y, fmaf(wq.z, d2.y, fmaf(wq.w, d3.y, acc.y))));
        acc.z = fmaf(wq.x, d0.z, fmaf(wq.y, d1.z, fmaf(wq.z, d2.z, fmaf(wq.w, d3.z, acc.z))));
        acc.w = fmaf(wq.x, d0.w, fmaf(wq.y, d1.w, fmaf(wq.z, d2.w, fmaf(wq.w, d3.w, acc.w))));
        if (lane16 == 0) zacc += (wq.x + wq.y) + (wq.z + wq.w);
    }

    int k = lane16 * 4;
    atomicAdd(&tsh[k + 0], acc.x);
    atomicAdd(&tsh[k + 1], acc.y);
    atomicAdd(&tsh[k + 2], acc.z);
    atomicAdd(&tsh[k + 3], acc.w);
    if (lane16 == 0) atomicAdd(&zsh, zacc);
    __syncthreads();

    if (tid < SIZE) atomicAdd(&g_t[tid], tsh[tid]);
    if (tid == 0) atomicAdd(&g_Z, zsh);

    // ---- last-block epilogue ----
    __threadfence();
    if (tid == 0) {
        unsigned int ticket = atomicAdd(&g_count, 1u);
        is_last = (ticket == K2_BLOCKS - 1);
    }
    __syncthreads();
    if (!is_last) return;

    float Z = *((volatile float*)&g_Z);
    if (tid < SIZE) agg[tid] = ((volatile float*)g_t)[tid] / Z;
    __syncthreads();

    // 4 threads per output row; each sums 16 terms, reduce within quad.
    int o = tid >> 2;
    int part = tid & 3;
    float s = 0.f;
#pragma unroll
    for (int kk = 0; kk < 16; kk++) {
        int idx = part * 16 + kk;
        s = fmaf(W[o * SIZE + idx], agg[idx], s);
    }
    s += __shfl_xor_sync(0xffffffffu, s, 2, 4);
    s += __shfl_xor_sync(0xffffffffu, s, 1, 4);
    if (part == 0) out[o] = 1.f / (1.f + expf(-s));
}

extern "C" void kernel_launch(void* const* d_in, const int* in_sizes, int n_in,
                              void* d_out, int out_size) {
    const float* x  = (const float*)d_in[0];  // (64)  [unused: softmax shift invariance]
    const float* nx = (const float*)d_in[1];  // (500000,64)
    const float* W  = (const float*)d_in[2];  // (64,64)
    const float* a  = (const float*)d_in[3];  // (128,1)
    float* out = (float*)d_out;               // (64)
    (void)x; (void)in_sizes; (void)n_in; (void)out_size;

    k1_energy_exp<<<K1_BLOCKS, K1_THREADS>>>(nx, W, a);
    k2_acc<<<K2_BLOCKS, 256>>>(nx, W, out);
}